// round 1
// baseline (speedup 1.0000x reference)
#include <cuda_runtime.h>
#include <cuda_bf16.h>
#include <cstdint>

// Problem constants
#define DMODEL 1024
#define HEADS  16
#define DK     64
#define BATCH  2
#define SEQ    2048
#define MROWS  (BATCH * SEQ)          // 4096

// ---------------- scratch (static device memory; no allocs) ----------------
__device__ float g_qh[BATCH * HEADS * SEQ * DK];   // [B*H][S][64]
__device__ float g_kh[BATCH * HEADS * SEQ * DK];
__device__ float g_vh[BATCH * HEADS * SEQ * DK];
__device__ float g_ctx[MROWS * DMODEL];            // [B*S][1024]

// ---------------- GEMM: Y = X @ W^T + bias -------------------------------
// X: [M,1024] row-major, W: [1024,1024] row-major (K-major for both).
// 64x64 tile, BK=32, 256 threads, 4x4 per thread.
// headSplit != 0 -> write to [B*H][S][DK] layout instead of [M,1024].
template <int HEADSPLIT>
__global__ __launch_bounds__(256) void gemm_xwt(
    const float* __restrict__ X, const float* __restrict__ W,
    const float* __restrict__ bias, float* __restrict__ Y)
{
    __shared__ float Xs[32][64];   // [k][m] transposed
    __shared__ float Ws[32][64];   // [k][n] transposed

    const int tid = threadIdx.x;
    const int tx = tid & 15;       // col group
    const int ty = tid >> 4;       // row group
    const int col0 = blockIdx.x * 64;
    const int row0 = blockIdx.y * 64;

    const int lr = tid >> 3;           // 0..31
    const int lc = (tid & 7) * 4;      // 0,4,...,28

    float acc[4][4];
#pragma unroll
    for (int i = 0; i < 4; i++)
#pragma unroll
        for (int j = 0; j < 4; j++) acc[i][j] = 0.f;

    const float* xp0 = X + (size_t)(row0 + lr) * DMODEL + lc;
    const float* wp0 = W + (size_t)(col0 + lr) * DMODEL + lc;

    for (int k0 = 0; k0 < DMODEL; k0 += 32) {
        // load X tile (64x32) and W tile (64x32), store transposed into smem
        float4 xa = *(const float4*)(xp0 + k0);
        float4 xb = *(const float4*)(xp0 + k0 + (size_t)32 * DMODEL);
        float4 wa = *(const float4*)(wp0 + k0);
        float4 wb = *(const float4*)(wp0 + k0 + (size_t)32 * DMODEL);

        Xs[lc + 0][lr] = xa.x; Xs[lc + 1][lr] = xa.y;
        Xs[lc + 2][lr] = xa.z; Xs[lc + 3][lr] = xa.w;
        Xs[lc + 0][lr + 32] = xb.x; Xs[lc + 1][lr + 32] = xb.y;
        Xs[lc + 2][lr + 32] = xb.z; Xs[lc + 3][lr + 32] = xb.w;
        Ws[lc + 0][lr] = wa.x; Ws[lc + 1][lr] = wa.y;
        Ws[lc + 2][lr] = wa.z; Ws[lc + 3][lr] = wa.w;
        Ws[lc + 0][lr + 32] = wb.x; Ws[lc + 1][lr + 32] = wb.y;
        Ws[lc + 2][lr + 32] = wb.z; Ws[lc + 3][lr + 32] = wb.w;
        __syncthreads();

#pragma unroll
        for (int kk = 0; kk < 32; kk++) {
            float4 a = *(const float4*)&Xs[kk][ty * 4];
            float4 b = *(const float4*)&Ws[kk][tx * 4];
            acc[0][0] += a.x * b.x; acc[0][1] += a.x * b.y; acc[0][2] += a.x * b.z; acc[0][3] += a.x * b.w;
            acc[1][0] += a.y * b.x; acc[1][1] += a.y * b.y; acc[1][2] += a.y * b.z; acc[1][3] += a.y * b.w;
            acc[2][0] += a.z * b.x; acc[2][1] += a.z * b.y; acc[2][2] += a.z * b.z; acc[2][3] += a.z * b.w;
            acc[3][0] += a.w * b.x; acc[3][1] += a.w * b.y; acc[3][2] += a.w * b.z; acc[3][3] += a.w * b.w;
        }
        __syncthreads();
    }

    // epilogue: add bias, write out (optionally head-split layout)
    float4 b4 = *(const float4*)&bias[col0 + tx * 4];
#pragma unroll
    for (int i = 0; i < 4; i++) {
        const int m = row0 + ty * 4 + i;
        float4 r;
        r.x = acc[i][0] + b4.x;
        r.y = acc[i][1] + b4.y;
        r.z = acc[i][2] + b4.z;
        r.w = acc[i][3] + b4.w;
        if (HEADSPLIT) {
            const int b = m >> 11;              // / SEQ
            const int s = m & (SEQ - 1);
            const int h = col0 >> 6;            // col0 is 64-aligned
            const int dk = tx * 4;
            float* dst = Y + (((size_t)(b * HEADS + h) * SEQ + s) * DK) + dk;
            *(float4*)dst = r;
        } else {
            *(float4*)(Y + (size_t)m * DMODEL + col0 + tx * 4) = r;
        }
    }
}

// ---------------- Flash attention ----------------------------------------
// One thread per query row; 128 query rows per block; key tiles of 32.
// Qh/Kh/Vh: [B*H][S][64]. Output written to g_ctx in [B][S][H*64] layout.
__global__ __launch_bounds__(128) void flash_attn(
    const float* __restrict__ Qh, const float* __restrict__ Kh,
    const float* __restrict__ Vh, float* __restrict__ Ctx)
{
    __shared__ float Ks[32 * 64];
    __shared__ float Vs[32 * 64];

    const int bh = blockIdx.y;                 // 0..B*H-1
    const int row = blockIdx.x * 128 + threadIdx.x;
    const int tid = threadIdx.x;
    const float scale = 0.125f;                // 1/sqrt(64)

    float q[64], O[64];
    {
        const float* qp = Qh + ((size_t)bh * SEQ + row) * DK;
#pragma unroll
        for (int i = 0; i < 16; i++) {
            float4 t = ((const float4*)qp)[i];
            q[i * 4 + 0] = t.x * scale; q[i * 4 + 1] = t.y * scale;
            q[i * 4 + 2] = t.z * scale; q[i * 4 + 3] = t.w * scale;
        }
    }
#pragma unroll
    for (int d = 0; d < 64; d++) O[d] = 0.f;

    float m = -1e30f, l = 0.f;

    for (int k0 = 0; k0 < SEQ; k0 += 32) {
        // cooperative K/V tile load (contiguous, matches global layout)
        const float4* kp = (const float4*)(Kh + ((size_t)bh * SEQ + k0) * DK);
        const float4* vp = (const float4*)(Vh + ((size_t)bh * SEQ + k0) * DK);
#pragma unroll
        for (int i = 0; i < 4; i++) {
            const int f4 = tid + i * 128;      // 0..511
            ((float4*)Ks)[f4] = kp[f4];
            ((float4*)Vs)[f4] = vp[f4];
        }
        __syncthreads();

        float s[32];
        float tmax = m;
#pragma unroll
        for (int j = 0; j < 32; j++) {
            float a0 = 0.f, a1 = 0.f, a2 = 0.f, a3 = 0.f;
            const float* kj = &Ks[j * 64];
#pragma unroll
            for (int d = 0; d < 64; d += 4) {
                float4 kv = *(const float4*)(kj + d);
                a0 += q[d + 0] * kv.x;
                a1 += q[d + 1] * kv.y;
                a2 += q[d + 2] * kv.z;
                a3 += q[d + 3] * kv.w;
            }
            float sj = (a0 + a1) + (a2 + a3);
            s[j] = sj;
            tmax = fmaxf(tmax, sj);
        }

        const float mnew = tmax;
        const float alpha = __expf(m - mnew);
        l *= alpha;
#pragma unroll
        for (int j = 0; j < 32; j++) {
            float p = __expf(s[j] - mnew);
            s[j] = p;
            l += p;
        }
#pragma unroll
        for (int d = 0; d < 64; d++) O[d] *= alpha;

#pragma unroll
        for (int j = 0; j < 32; j++) {
            const float p = s[j];
            const float* vj = &Vs[j * 64];
#pragma unroll
            for (int d = 0; d < 64; d += 4) {
                float4 vv = *(const float4*)(vj + d);
                O[d + 0] += p * vv.x;
                O[d + 1] += p * vv.y;
                O[d + 2] += p * vv.z;
                O[d + 3] += p * vv.w;
            }
        }
        m = mnew;
        __syncthreads();
    }

    const float inv = 1.f / l;
    const int b = bh >> 4;
    const int h = bh & 15;
    float* op = Ctx + ((size_t)b * SEQ + row) * DMODEL + h * DK;
#pragma unroll
    for (int d = 0; d < 64; d += 4) {
        float4 r;
        r.x = O[d + 0] * inv; r.y = O[d + 1] * inv;
        r.z = O[d + 2] * inv; r.w = O[d + 3] * inv;
        *(float4*)(op + d) = r;
    }
}

// ---------------- launch ---------------------------------------------------
extern "C" void kernel_launch(void* const* d_in, const int* in_sizes, int n_in,
                              void* d_out, int out_size)
{
    (void)in_sizes; (void)n_in; (void)out_size;
    const float* q    = (const float*)d_in[0];
    const float* k    = (const float*)d_in[1];
    const float* v    = (const float*)d_in[2];
    // d_in[3] = mask: all-true by construction -> skipped
    const float* wq_w = (const float*)d_in[4];
    const float* wq_b = (const float*)d_in[5];
    const float* wk_w = (const float*)d_in[6];
    const float* wk_b = (const float*)d_in[7];
    const float* wv_w = (const float*)d_in[8];
    const float* wv_b = (const float*)d_in[9];
    const float* wo_w = (const float*)d_in[10];
    const float* wo_b = (const float*)d_in[11];
    float* out = (float*)d_out;

    float *qh, *kh, *vh, *ctx;
    cudaGetSymbolAddress((void**)&qh,  g_qh);
    cudaGetSymbolAddress((void**)&kh,  g_kh);
    cudaGetSymbolAddress((void**)&vh,  g_vh);
    cudaGetSymbolAddress((void**)&ctx, g_ctx);

    dim3 ggrid(DMODEL / 64, MROWS / 64);   // (16, 64)
    dim3 gblk(256);

    gemm_xwt<1><<<ggrid, gblk>>>(q, wq_w, wq_b, qh);
    gemm_xwt<1><<<ggrid, gblk>>>(k, wk_w, wk_b, kh);
    gemm_xwt<1><<<ggrid, gblk>>>(v, wv_w, wv_b, vh);

    dim3 agrid(SEQ / 128, BATCH * HEADS); // (16, 32)
    flash_attn<<<agrid, 128>>>(qh, kh, vh, ctx);

    gemm_xwt<0><<<ggrid, gblk>>>(ctx, wo_w, wo_b, out);
}

// round 5
// speedup vs baseline: 1.4785x; 1.4785x over previous
#include <cuda_runtime.h>
#include <cuda_bf16.h>
#include <cstdint>

// Problem constants
#define DMODEL 1024
#define HEADS  16
#define DK     64
#define BATCH  2
#define SEQ    2048
#define MROWS  (BATCH * SEQ)          // 4096

// ---------------- scratch (static device memory; no allocs) ----------------
__device__ float g_qh[BATCH * HEADS * SEQ * DK];   // [B*H][S][64]
__device__ float g_kh[BATCH * HEADS * SEQ * DK];
__device__ float g_vh[BATCH * HEADS * SEQ * DK];
__device__ float g_ctx[MROWS * DMODEL];            // [B*S][1024]

// bf16 hi/lo split scratch
__device__ __nv_bfloat16 g_qhi[MROWS * DMODEL], g_qlo[MROWS * DMODEL];
__device__ __nv_bfloat16 g_khi[MROWS * DMODEL], g_klo[MROWS * DMODEL];
__device__ __nv_bfloat16 g_vhi[MROWS * DMODEL], g_vlo[MROWS * DMODEL];
__device__ __nv_bfloat16 g_chi[MROWS * DMODEL], g_clo[MROWS * DMODEL];
__device__ __nv_bfloat16 g_wqhi[DMODEL * DMODEL], g_wqlo[DMODEL * DMODEL];
__device__ __nv_bfloat16 g_wkhi[DMODEL * DMODEL], g_wklo[DMODEL * DMODEL];
__device__ __nv_bfloat16 g_wvhi[DMODEL * DMODEL], g_wvlo[DMODEL * DMODEL];
__device__ __nv_bfloat16 g_wohi[DMODEL * DMODEL], g_wolo[DMODEL * DMODEL];

// ---------------- helpers ---------------------------------------------------
__device__ __forceinline__ void mma16816(float* c, const uint32_t* a, const uint32_t* b) {
    asm volatile(
        "mma.sync.aligned.m16n8k16.row.col.f32.bf16.bf16.f32 "
        "{%0,%1,%2,%3}, {%4,%5,%6,%7}, {%8,%9}, {%0,%1,%2,%3};"
        : "+f"(c[0]), "+f"(c[1]), "+f"(c[2]), "+f"(c[3])
        : "r"(a[0]), "r"(a[1]), "r"(a[2]), "r"(a[3]), "r"(b[0]), "r"(b[1]));
}

// ---------------- split fp32 -> bf16 hi/lo ---------------------------------
__global__ __launch_bounds__(256) void split_bf16_k(
    const float4* __restrict__ x, uint2* __restrict__ hi,
    uint2* __restrict__ lo, int n4)
{
    int i = blockIdx.x * blockDim.x + threadIdx.x;
    if (i >= n4) return;
    float4 v = x[i];
    float f[4] = {v.x, v.y, v.z, v.w};
    unsigned short hb[4], lb[4];
#pragma unroll
    for (int j = 0; j < 4; j++) {
        __nv_bfloat16 h = __float2bfloat16(f[j]);
        float r = f[j] - __bfloat162float(h);
        __nv_bfloat16 l = __float2bfloat16(r);
        hb[j] = __bfloat16_as_ushort(h);
        lb[j] = __bfloat16_as_ushort(l);
    }
    hi[i] = make_uint2((uint32_t)hb[0] | ((uint32_t)hb[1] << 16),
                       (uint32_t)hb[2] | ((uint32_t)hb[3] << 16));
    lo[i] = make_uint2((uint32_t)lb[0] | ((uint32_t)lb[1] << 16),
                       (uint32_t)lb[2] | ((uint32_t)lb[3] << 16));
}

// ---------------- mma.sync bf16 GEMM: Y = X @ W^T + bias -------------------
// 128x128 tile, BK=32 bf16 per chunk, *** 32 chunks => K=1024 *** (R3/R4 bug
// was 16 chunks = K=512). 8 warps each 64(M)x32(N). Single 40KB smem buffer.
// Register-prefetch pipeline: LDG chunk c+1 while computing chunk c.
// 80B smem rows: (qr*20+qc) mod 32 distinct -> conflict-free fragment LDS.
#define TSTRIDE   80
#define TILE_B    (128 * TSTRIDE)      // 10240
#define GEMM_SMEM (4 * TILE_B)         // 40960: Ahi | Alo | Bhi | Blo
#define NCHUNK    32                   // 32 * 32 = 1024 = DMODEL

template <int HEADSPLIT>
__global__ __launch_bounds__(256) void gemm_mma(
    const __nv_bfloat16* __restrict__ Ahi, const __nv_bfloat16* __restrict__ Alo,
    const __nv_bfloat16* __restrict__ Bhi, const __nv_bfloat16* __restrict__ Blo,
    const float* __restrict__ bias, float* __restrict__ Y)
{
    extern __shared__ __align__(16) char smem_raw[];

    const int tid  = threadIdx.x;
    const int wid  = tid >> 5, lane = tid & 31;
    const int wm   = wid & 1;            // 2 warps along M (64 each)
    const int wn   = wid >> 1;           // 4 warps along N (32 each)
    const int qr   = lane >> 2;          // 0..7
    const int qc   = lane & 3;           // 0..3
    const int row0 = blockIdx.y * 128;
    const int col0 = blockIdx.x * 128;

    float acc[4][4][4];                  // [mtile16][ntile8][c0..c3]
#pragma unroll
    for (int a = 0; a < 4; a++)
#pragma unroll
        for (int b = 0; b < 4; b++)
#pragma unroll
            for (int c = 0; c < 4; c++) acc[a][b][c] = 0.f;

    // per-thread global-load slots: u = tid + i*256; arr=u>>9, r=(u&511)>>2, ch=u&3
    float4 pf[8];

    auto ldg_chunk = [&](int c) {
#pragma unroll
        for (int i = 0; i < 8; i++) {
            const int u   = tid + i * 256;
            const int arr = u >> 9;
            const int r   = (u & 511) >> 2;
            const int ch  = u & 3;
            const __nv_bfloat16* src =
                (arr == 0) ? Ahi : (arr == 1) ? Alo : (arr == 2) ? Bhi : Blo;
            const int grow = ((arr < 2) ? row0 : col0) + r;
            pf[i] = *(const float4*)(src + (size_t)grow * DMODEL + c * 32 + ch * 8);
        }
    };
    auto st_chunk = [&]() {
#pragma unroll
        for (int i = 0; i < 8; i++) {
            const int u   = tid + i * 256;
            const int arr = u >> 9;
            const int r   = (u & 511) >> 2;
            const int ch  = u & 3;
            *(float4*)(smem_raw + arr * TILE_B + r * TSTRIDE + ch * 16) = pf[i];
        }
    };

    ldg_chunk(0);

#pragma unroll 1
    for (int c = 0; c < NCHUNK; c++) {
        __syncthreads();                  // previous compute done
        st_chunk();
        __syncthreads();                  // tile visible to all
        if (c < NCHUNK - 1) ldg_chunk(c + 1);  // overlap with compute below

#pragma unroll
        for (int ks = 0; ks < 2; ks++) {
            const int kb = ks * 32 + qc * 4;   // byte offset of this lane's k pair

            uint32_t bh[4][2], bl[4][2];
#pragma unroll
            for (int nt = 0; nt < 4; nt++) {
                const char* bp = smem_raw + 2 * TILE_B
                               + (wn * 32 + nt * 8 + qr) * TSTRIDE + kb;
                bh[nt][0] = *(const uint32_t*)bp;            // k 0-7 half
                bh[nt][1] = *(const uint32_t*)(bp + 16);     // k 8-15 half
                bl[nt][0] = *(const uint32_t*)(bp + TILE_B);
                bl[nt][1] = *(const uint32_t*)(bp + TILE_B + 16);
            }
#pragma unroll
            for (int mt = 0; mt < 4; mt++) {
                const char* ap = smem_raw
                               + (wm * 64 + mt * 16 + qr) * TSTRIDE + kb;
                uint32_t ah[4], al[4];
                ah[0] = *(const uint32_t*)ap;                     // (r, k0)
                ah[1] = *(const uint32_t*)(ap + 8 * TSTRIDE);     // (r+8, k0)
                ah[2] = *(const uint32_t*)(ap + 16);              // (r, k8)
                ah[3] = *(const uint32_t*)(ap + 8 * TSTRIDE + 16);// (r+8, k8)
                al[0] = *(const uint32_t*)(ap + TILE_B);
                al[1] = *(const uint32_t*)(ap + TILE_B + 8 * TSTRIDE);
                al[2] = *(const uint32_t*)(ap + TILE_B + 16);
                al[3] = *(const uint32_t*)(ap + TILE_B + 8 * TSTRIDE + 16);
#pragma unroll
                for (int nt = 0; nt < 4; nt++) {
                    mma16816(acc[mt][nt], ah, bh[nt]);
                    mma16816(acc[mt][nt], ah, bl[nt]);
                    mma16816(acc[mt][nt], al, bh[nt]);
                }
            }
        }
    }

    // ---- epilogue ----
#pragma unroll
    for (int mt = 0; mt < 4; mt++) {
#pragma unroll
        for (int nt = 0; nt < 4; nt++) {
            const int col = col0 + wn * 32 + nt * 8 + qc * 2;
            float2 bv = *(const float2*)&bias[col];
#pragma unroll
            for (int h = 0; h < 2; h++) {
                const int m = row0 + wm * 64 + mt * 16 + qr + h * 8;
                float2 r;
                r.x = acc[mt][nt][h * 2 + 0] + bv.x;
                r.y = acc[mt][nt][h * 2 + 1] + bv.y;
                if (HEADSPLIT) {
                    const int b = m >> 11, s = m & (SEQ - 1);
                    const int hh = col >> 6, dk = col & 63;
                    *(float2*)(Y + (((size_t)(b * HEADS + hh) * SEQ + s) * DK) + dk) = r;
                } else {
                    *(float2*)(Y + (size_t)m * DMODEL + col) = r;
                }
            }
        }
    }
}

// ---------------- Flash attention (unchanged from R1 — passing) ------------
__global__ __launch_bounds__(128) void flash_attn(
    const float* __restrict__ Qh, const float* __restrict__ Kh,
    const float* __restrict__ Vh, float* __restrict__ Ctx)
{
    __shared__ float Ks[32 * 64];
    __shared__ float Vs[32 * 64];

    const int bh = blockIdx.y;
    const int row = blockIdx.x * 128 + threadIdx.x;
    const int tid = threadIdx.x;
    const float scale = 0.125f;

    float q[64], O[64];
    {
        const float* qp = Qh + ((size_t)bh * SEQ + row) * DK;
#pragma unroll
        for (int i = 0; i < 16; i++) {
            float4 t = ((const float4*)qp)[i];
            q[i * 4 + 0] = t.x * scale; q[i * 4 + 1] = t.y * scale;
            q[i * 4 + 2] = t.z * scale; q[i * 4 + 3] = t.w * scale;
        }
    }
#pragma unroll
    for (int d = 0; d < 64; d++) O[d] = 0.f;

    float m = -1e30f, l = 0.f;

    for (int k0 = 0; k0 < SEQ; k0 += 32) {
        const float4* kp = (const float4*)(Kh + ((size_t)bh * SEQ + k0) * DK);
        const float4* vp = (const float4*)(Vh + ((size_t)bh * SEQ + k0) * DK);
#pragma unroll
        for (int i = 0; i < 4; i++) {
            const int f4 = tid + i * 128;
            ((float4*)Ks)[f4] = kp[f4];
            ((float4*)Vs)[f4] = vp[f4];
        }
        __syncthreads();

        float s[32];
        float tmax = m;
#pragma unroll
        for (int j = 0; j < 32; j++) {
            float a0 = 0.f, a1 = 0.f, a2 = 0.f, a3 = 0.f;
            const float* kj = &Ks[j * 64];
#pragma unroll
            for (int d = 0; d < 64; d += 4) {
                float4 kv = *(const float4*)(kj + d);
                a0 += q[d + 0] * kv.x;
                a1 += q[d + 1] * kv.y;
                a2 += q[d + 2] * kv.z;
                a3 += q[d + 3] * kv.w;
            }
            float sj = (a0 + a1) + (a2 + a3);
            s[j] = sj;
            tmax = fmaxf(tmax, sj);
        }

        const float mnew = tmax;
        const float alpha = __expf(m - mnew);
        l *= alpha;
#pragma unroll
        for (int j = 0; j < 32; j++) {
            float p = __expf(s[j] - mnew);
            s[j] = p;
            l += p;
        }
#pragma unroll
        for (int d = 0; d < 64; d++) O[d] *= alpha;

#pragma unroll
        for (int j = 0; j < 32; j++) {
            const float p = s[j];
            const float* vj = &Vs[j * 64];
#pragma unroll
            for (int d = 0; d < 64; d += 4) {
                float4 vv = *(const float4*)(vj + d);
                O[d + 0] += p * vv.x;
                O[d + 1] += p * vv.y;
                O[d + 2] += p * vv.z;
                O[d + 3] += p * vv.w;
            }
        }
        m = mnew;
        __syncthreads();
    }

    const float inv = 1.f / l;
    const int b = bh >> 4;
    const int h = bh & 15;
    float* op = Ctx + ((size_t)b * SEQ + row) * DMODEL + h * DK;
#pragma unroll
    for (int d = 0; d < 64; d += 4) {
        float4 r;
        r.x = O[d + 0] * inv; r.y = O[d + 1] * inv;
        r.z = O[d + 2] * inv; r.w = O[d + 3] * inv;
        *(float4*)(op + d) = r;
    }
}

// ---------------- launch ---------------------------------------------------
extern "C" void kernel_launch(void* const* d_in, const int* in_sizes, int n_in,
                              void* d_out, int out_size)
{
    (void)in_sizes; (void)n_in; (void)out_size;
    const float* q    = (const float*)d_in[0];
    const float* k    = (const float*)d_in[1];
    const float* v    = (const float*)d_in[2];
    const float* wq_w = (const float*)d_in[4];
    const float* wq_b = (const float*)d_in[5];
    const float* wk_w = (const float*)d_in[6];
    const float* wk_b = (const float*)d_in[7];
    const float* wv_w = (const float*)d_in[8];
    const float* wv_b = (const float*)d_in[9];
    const float* wo_w = (const float*)d_in[10];
    const float* wo_b = (const float*)d_in[11];
    float* out = (float*)d_out;

    float *qh, *kh, *vh, *ctx;
    cudaGetSymbolAddress((void**)&qh,  g_qh);
    cudaGetSymbolAddress((void**)&kh,  g_kh);
    cudaGetSymbolAddress((void**)&vh,  g_vh);
    cudaGetSymbolAddress((void**)&ctx, g_ctx);

    __nv_bfloat16 *qhi, *qlo, *khi, *klo, *vhi, *vlo, *chi, *clo;
    __nv_bfloat16 *wqhi, *wqlo, *wkhi, *wklo, *wvhi, *wvlo, *wohi, *wolo;
    cudaGetSymbolAddress((void**)&qhi, g_qhi);  cudaGetSymbolAddress((void**)&qlo, g_qlo);
    cudaGetSymbolAddress((void**)&khi, g_khi);  cudaGetSymbolAddress((void**)&klo, g_klo);
    cudaGetSymbolAddress((void**)&vhi, g_vhi);  cudaGetSymbolAddress((void**)&vlo, g_vlo);
    cudaGetSymbolAddress((void**)&chi, g_chi);  cudaGetSymbolAddress((void**)&clo, g_clo);
    cudaGetSymbolAddress((void**)&wqhi, g_wqhi); cudaGetSymbolAddress((void**)&wqlo, g_wqlo);
    cudaGetSymbolAddress((void**)&wkhi, g_wkhi); cudaGetSymbolAddress((void**)&wklo, g_wklo);
    cudaGetSymbolAddress((void**)&wvhi, g_wvhi); cudaGetSymbolAddress((void**)&wvlo, g_wvlo);
    cudaGetSymbolAddress((void**)&wohi, g_wohi); cudaGetSymbolAddress((void**)&wolo, g_wolo);

    const int nAct4 = MROWS * DMODEL / 4;
    const int nW4   = DMODEL * DMODEL / 4;

    split_bf16_k<<<(nAct4 + 255) / 256, 256>>>((const float4*)q, (uint2*)qhi, (uint2*)qlo, nAct4);
    split_bf16_k<<<(nAct4 + 255) / 256, 256>>>((const float4*)k, (uint2*)khi, (uint2*)klo, nAct4);
    split_bf16_k<<<(nAct4 + 255) / 256, 256>>>((const float4*)v, (uint2*)vhi, (uint2*)vlo, nAct4);
    split_bf16_k<<<(nW4 + 255) / 256, 256>>>((const float4*)wq_w, (uint2*)wqhi, (uint2*)wqlo, nW4);
    split_bf16_k<<<(nW4 + 255) / 256, 256>>>((const float4*)wk_w, (uint2*)wkhi, (uint2*)wklo, nW4);
    split_bf16_k<<<(nW4 + 255) / 256, 256>>>((const float4*)wv_w, (uint2*)wvhi, (uint2*)wvlo, nW4);
    split_bf16_k<<<(nW4 + 255) / 256, 256>>>((const float4*)wo_w, (uint2*)wohi, (uint2*)wolo, nW4);

    dim3 ggrid(DMODEL / 128, MROWS / 128);   // (8, 32)
    gemm_mma<1><<<ggrid, 256, GEMM_SMEM>>>(qhi, qlo, wqhi, wqlo, wq_b, qh);
    gemm_mma<1><<<ggrid, 256, GEMM_SMEM>>>(khi, klo, wkhi, wklo, wk_b, kh);
    gemm_mma<1><<<ggrid, 256, GEMM_SMEM>>>(vhi, vlo, wvhi, wvlo, wv_b, vh);

    dim3 agrid(SEQ / 128, BATCH * HEADS);    // (16, 32)
    flash_attn<<<agrid, 128>>>(qh, kh, vh, ctx);

    split_bf16_k<<<(nAct4 + 255) / 256, 256>>>((const float4*)ctx, (uint2*)chi, (uint2*)clo, nAct4);
    gemm_mma<0><<<ggrid, 256, GEMM_SMEM>>>(chi, clo, wohi, wolo, wo_b, out);
}

// round 6
// speedup vs baseline: 3.0298x; 2.0493x over previous
#include <cuda_runtime.h>
#include <cuda_bf16.h>
#include <cstdint>

// Problem constants
#define DMODEL 1024
#define HEADS  16
#define DK     64
#define BATCH  2
#define SEQ    2048
#define MROWS  (BATCH * SEQ)          // 4096
#define BH     (BATCH * HEADS)        // 32

// ---------------- scratch (static device memory; no allocs) ----------------
__device__ float g_ctx[MROWS * DMODEL];            // [B*S][1024]

// input splits (GEMM A operands)
__device__ __nv_bfloat16 g_qhi[MROWS * DMODEL], g_qlo[MROWS * DMODEL];
__device__ __nv_bfloat16 g_khi[MROWS * DMODEL], g_klo[MROWS * DMODEL];
__device__ __nv_bfloat16 g_vhi[MROWS * DMODEL], g_vlo[MROWS * DMODEL];
__device__ __nv_bfloat16 g_chi[MROWS * DMODEL], g_clo[MROWS * DMODEL];
// weight splits
__device__ __nv_bfloat16 g_wqhi[DMODEL * DMODEL], g_wqlo[DMODEL * DMODEL];
__device__ __nv_bfloat16 g_wkhi[DMODEL * DMODEL], g_wklo[DMODEL * DMODEL];
__device__ __nv_bfloat16 g_wvhi[DMODEL * DMODEL], g_wvlo[DMODEL * DMODEL];
__device__ __nv_bfloat16 g_wohi[DMODEL * DMODEL], g_wolo[DMODEL * DMODEL];
// projection outputs, pre-split bf16 (flash consumes these directly)
__device__ __nv_bfloat16 g_qshi[BH * SEQ * DK], g_qslo[BH * SEQ * DK]; // [bh][s][dk]
__device__ __nv_bfloat16 g_kshi[BH * SEQ * DK], g_kslo[BH * SEQ * DK]; // [bh][s][dk]
__device__ __nv_bfloat16 g_vthi[BH * DK * SEQ], g_vtlo[BH * DK * SEQ]; // [bh][dk][s]

// ---------------- helpers ---------------------------------------------------
__device__ __forceinline__ void mma16816(float* c, const uint32_t* a, const uint32_t* b) {
    asm volatile(
        "mma.sync.aligned.m16n8k16.row.col.f32.bf16.bf16.f32 "
        "{%0,%1,%2,%3}, {%4,%5,%6,%7}, {%8,%9}, {%0,%1,%2,%3};"
        : "+f"(c[0]), "+f"(c[1]), "+f"(c[2]), "+f"(c[3])
        : "r"(a[0]), "r"(a[1]), "r"(a[2]), "r"(a[3]), "r"(b[0]), "r"(b[1]));
}
__device__ __forceinline__ float ex2f(float x) {
    float y; asm("ex2.approx.ftz.f32 %0, %1;" : "=f"(y) : "f"(x)); return y;
}
__device__ __forceinline__ uint32_t pack_bf2(float a, float b) {
    __nv_bfloat162 t = __floats2bfloat162_rn(a, b);
    return *reinterpret_cast<uint32_t*>(&t);
}

// ---------------- split fp32 -> bf16 hi/lo ---------------------------------
__global__ __launch_bounds__(256) void split_bf16_k(
    const float4* __restrict__ x, uint2* __restrict__ hi,
    uint2* __restrict__ lo, int n4)
{
    int i = blockIdx.x * blockDim.x + threadIdx.x;
    if (i >= n4) return;
    float4 v = x[i];
    float f[4] = {v.x, v.y, v.z, v.w};
    unsigned short hb[4], lb[4];
#pragma unroll
    for (int j = 0; j < 4; j++) {
        __nv_bfloat16 h = __float2bfloat16(f[j]);
        float r = f[j] - __bfloat162float(h);
        __nv_bfloat16 l = __float2bfloat16(r);
        hb[j] = __bfloat16_as_ushort(h);
        lb[j] = __bfloat16_as_ushort(l);
    }
    hi[i] = make_uint2((uint32_t)hb[0] | ((uint32_t)hb[1] << 16),
                       (uint32_t)hb[2] | ((uint32_t)hb[3] << 16));
    lo[i] = make_uint2((uint32_t)lb[0] | ((uint32_t)lb[1] << 16),
                       (uint32_t)lb[2] | ((uint32_t)lb[3] << 16));
}

// ---------------- mma.sync bf16 GEMM: Y = (X @ W^T + bias) * scale ---------
// 128x128 tile, BK=32, 32 chunks (K=1024), 8 warps each 64(M)x32(N).
// MODE 0: fp32 Y[m][1024].  MODE 1: bf16 hi/lo head-split [bh][s][64].
// MODE 2: bf16 hi/lo transposed head-split [bh][64][s]  (for V).
#define TSTRIDE   80
#define TILE_B    (128 * TSTRIDE)      // 10240
#define GEMM_SMEM (4 * TILE_B)         // 40960: Ahi | Alo | Bhi | Blo
#define NCHUNK    32

template <int MODE>
__global__ __launch_bounds__(256) void gemm_mma(
    const __nv_bfloat16* __restrict__ Ahi, const __nv_bfloat16* __restrict__ Alo,
    const __nv_bfloat16* __restrict__ Bhi, const __nv_bfloat16* __restrict__ Blo,
    const float* __restrict__ bias, float scale,
    float* __restrict__ Yf,
    __nv_bfloat16* __restrict__ Yhi, __nv_bfloat16* __restrict__ Ylo)
{
    extern __shared__ __align__(16) char smem_raw[];

    const int tid  = threadIdx.x;
    const int wid  = tid >> 5, lane = tid & 31;
    const int wm   = wid & 1;
    const int wn   = wid >> 1;
    const int qr   = lane >> 2;
    const int qc   = lane & 3;
    const int row0 = blockIdx.y * 128;
    const int col0 = blockIdx.x * 128;

    float acc[4][4][4];
#pragma unroll
    for (int a = 0; a < 4; a++)
#pragma unroll
        for (int b = 0; b < 4; b++)
#pragma unroll
            for (int c = 0; c < 4; c++) acc[a][b][c] = 0.f;

    float4 pf[8];
    auto ldg_chunk = [&](int c) {
#pragma unroll
        for (int i = 0; i < 8; i++) {
            const int u   = tid + i * 256;
            const int arr = u >> 9;
            const int r   = (u & 511) >> 2;
            const int ch  = u & 3;
            const __nv_bfloat16* src =
                (arr == 0) ? Ahi : (arr == 1) ? Alo : (arr == 2) ? Bhi : Blo;
            const int grow = ((arr < 2) ? row0 : col0) + r;
            pf[i] = *(const float4*)(src + (size_t)grow * DMODEL + c * 32 + ch * 8);
        }
    };
    auto st_chunk = [&]() {
#pragma unroll
        for (int i = 0; i < 8; i++) {
            const int u   = tid + i * 256;
            const int arr = u >> 9;
            const int r   = (u & 511) >> 2;
            const int ch  = u & 3;
            *(float4*)(smem_raw + arr * TILE_B + r * TSTRIDE + ch * 16) = pf[i];
        }
    };

    ldg_chunk(0);

#pragma unroll 1
    for (int c = 0; c < NCHUNK; c++) {
        __syncthreads();
        st_chunk();
        __syncthreads();
        if (c < NCHUNK - 1) ldg_chunk(c + 1);

#pragma unroll
        for (int ks = 0; ks < 2; ks++) {
            const int kb = ks * 32 + qc * 4;

            uint32_t bh_[4][2], bl_[4][2];
#pragma unroll
            for (int nt = 0; nt < 4; nt++) {
                const char* bp = smem_raw + 2 * TILE_B
                               + (wn * 32 + nt * 8 + qr) * TSTRIDE + kb;
                bh_[nt][0] = *(const uint32_t*)bp;
                bh_[nt][1] = *(const uint32_t*)(bp + 16);
                bl_[nt][0] = *(const uint32_t*)(bp + TILE_B);
                bl_[nt][1] = *(const uint32_t*)(bp + TILE_B + 16);
            }
#pragma unroll
            for (int mt = 0; mt < 4; mt++) {
                const char* ap = smem_raw + (wm * 64 + mt * 16 + qr) * TSTRIDE + kb;
                uint32_t ah[4], al[4];
                ah[0] = *(const uint32_t*)ap;
                ah[1] = *(const uint32_t*)(ap + 8 * TSTRIDE);
                ah[2] = *(const uint32_t*)(ap + 16);
                ah[3] = *(const uint32_t*)(ap + 8 * TSTRIDE + 16);
                al[0] = *(const uint32_t*)(ap + TILE_B);
                al[1] = *(const uint32_t*)(ap + TILE_B + 8 * TSTRIDE);
                al[2] = *(const uint32_t*)(ap + TILE_B + 16);
                al[3] = *(const uint32_t*)(ap + TILE_B + 8 * TSTRIDE + 16);
#pragma unroll
                for (int nt = 0; nt < 4; nt++) {
                    mma16816(acc[mt][nt], ah, bh_[nt]);
                    mma16816(acc[mt][nt], ah, bl_[nt]);
                    mma16816(acc[mt][nt], al, bh_[nt]);
                }
            }
        }
    }

    // ---- epilogue ----
#pragma unroll
    for (int mt = 0; mt < 4; mt++) {
#pragma unroll
        for (int nt = 0; nt < 4; nt++) {
            const int col = col0 + wn * 32 + nt * 8 + qc * 2;
            float2 bv = *(const float2*)&bias[col];
#pragma unroll
            for (int h = 0; h < 2; h++) {
                const int m = row0 + wm * 64 + mt * 16 + qr + h * 8;
                float v0 = (acc[mt][nt][h * 2 + 0] + bv.x) * scale;
                float v1 = (acc[mt][nt][h * 2 + 1] + bv.y) * scale;
                if (MODE == 0) {
                    float2 r; r.x = v0; r.y = v1;
                    *(float2*)(Yf + (size_t)m * DMODEL + col) = r;
                } else {
                    const int b  = m >> 11, s = m & (SEQ - 1);
                    const int hh = col >> 6, dk = col & 63;
                    __nv_bfloat16 h0 = __float2bfloat16(v0);
                    __nv_bfloat16 h1 = __float2bfloat16(v1);
                    float r0 = v0 - __bfloat162float(h0);
                    float r1 = v1 - __bfloat162float(h1);
                    __nv_bfloat16 l0 = __float2bfloat16(r0);
                    __nv_bfloat16 l1 = __float2bfloat16(r1);
                    if (MODE == 1) {
                        const size_t idx = ((size_t)(b * HEADS + hh) * SEQ + s) * DK + dk;
                        *(uint32_t*)(Yhi + idx) =
                            (uint32_t)__bfloat16_as_ushort(h0) |
                            ((uint32_t)__bfloat16_as_ushort(h1) << 16);
                        *(uint32_t*)(Ylo + idx) =
                            (uint32_t)__bfloat16_as_ushort(l0) |
                            ((uint32_t)__bfloat16_as_ushort(l1) << 16);
                    } else {           // MODE 2: transposed [bh][dk][s]
                        const size_t base = ((size_t)(b * HEADS + hh) * DK + dk) * SEQ + s;
                        Yhi[base]       = h0;  Yhi[base + SEQ] = h1;
                        Ylo[base]       = l0;  Ylo[base + SEQ] = l1;
                    }
                }
            }
        }
    }
}

// ---------------- tensor-core flash attention -------------------------------
// Grid: (SEQ/128, BH). 8 warps; each warp owns 16 query rows.
// Bc = 64 keys per iteration. Q pre-scaled by (1/8)*log2(e) in projection.
// Smem tiles: Khi|Klo [64 key][64 dk], Vthi|Vtlo [64 dk][64 key]; 144B rows.
#define ATS   144
#define KTILE (64 * ATS)               // 9216

__global__ __launch_bounds__(256) void flash_mma(
    const __nv_bfloat16* __restrict__ Qhi, const __nv_bfloat16* __restrict__ Qlo,
    const __nv_bfloat16* __restrict__ Khi, const __nv_bfloat16* __restrict__ Klo,
    const __nv_bfloat16* __restrict__ Vthi, const __nv_bfloat16* __restrict__ Vtlo,
    float* __restrict__ Ctx)
{
    __shared__ __align__(16) char sm[4 * KTILE];   // 36864

    const int tid = threadIdx.x, wid = tid >> 5, lane = tid & 31;
    const int qr = lane >> 2, qc = lane & 3;
    const int bh = blockIdx.y;
    const int s0 = blockIdx.x * 128;
    const int b  = bh >> 4, h = bh & 15;

    // ---- stage Q tile (hi at 0, lo at 2*KTILE), extract A-fragments ----
#pragma unroll
    for (int i = 0; i < 8; i++) {
        int u = tid + i * 256;          // 0..2047
        int arr = u >> 10;              // 0=hi 1=lo
        int idx = u & 1023, r = idx >> 3, ch = idx & 7;
        const __nv_bfloat16* src = arr ? Qlo : Qhi;
        *(float4*)(sm + arr * 2 * KTILE + r * ATS + ch * 16) =
            *(const float4*)(src + ((size_t)bh * SEQ + s0 + r) * DK + ch * 8);
    }
    __syncthreads();
    uint32_t qfh[4][4], qfl[4][4];
    {
        const char* base = sm + (wid * 16 + qr) * ATS;
#pragma unroll
        for (int kt = 0; kt < 4; kt++) {
            const int off = kt * 32 + qc * 4;
            qfh[kt][0] = *(const uint32_t*)(base + off);
            qfh[kt][1] = *(const uint32_t*)(base + 8 * ATS + off);
            qfh[kt][2] = *(const uint32_t*)(base + off + 16);
            qfh[kt][3] = *(const uint32_t*)(base + 8 * ATS + off + 16);
            qfl[kt][0] = *(const uint32_t*)(base + 2 * KTILE + off);
            qfl[kt][1] = *(const uint32_t*)(base + 2 * KTILE + 8 * ATS + off);
            qfl[kt][2] = *(const uint32_t*)(base + 2 * KTILE + off + 16);
            qfl[kt][3] = *(const uint32_t*)(base + 2 * KTILE + 8 * ATS + off + 16);
        }
    }
    __syncthreads();

    float O[8][4];
#pragma unroll
    for (int nt = 0; nt < 8; nt++)
#pragma unroll
        for (int c = 0; c < 4; c++) O[nt][c] = 0.f;
    float m0 = -1e30f, m1 = -1e30f, l0 = 0.f, l1 = 0.f;

    float4 pf[8];
    auto ldgKV = [&](int t) {
        const int j0 = t * 64;
#pragma unroll
        for (int i = 0; i < 8; i++) {
            int u = tid + i * 256;
            int arr = u >> 9;           // 0=Khi 1=Klo 2=Vthi 3=Vtlo
            int idx = u & 511, r = idx >> 3, ch = idx & 7;
            const __nv_bfloat16* src =
                (arr == 0) ? Khi : (arr == 1) ? Klo : (arr == 2) ? Vthi : Vtlo;
            size_t g = (arr < 2)
                ? (((size_t)bh * SEQ + j0 + r) * DK + ch * 8)
                : (((size_t)bh * DK + r) * SEQ + j0 + ch * 8);
            pf[i] = *(const float4*)(src + g);
        }
    };
    auto stKV = [&]() {
#pragma unroll
        for (int i = 0; i < 8; i++) {
            int u = tid + i * 256;
            int arr = u >> 9;
            int idx = u & 511, r = idx >> 3, ch = idx & 7;
            *(float4*)(sm + arr * KTILE + r * ATS + ch * 16) = pf[i];
        }
    };

    ldgKV(0);

#pragma unroll 1
    for (int t = 0; t < SEQ / 64; t++) {
        __syncthreads();
        stKV();
        __syncthreads();
        if (t < SEQ / 64 - 1) ldgKV(t + 1);

        // ---- S = Q K^T (3-product split), base-2 domain ----
        float S[8][4];
#pragma unroll
        for (int nt = 0; nt < 8; nt++)
#pragma unroll
            for (int c = 0; c < 4; c++) S[nt][c] = 0.f;

#pragma unroll
        for (int kt = 0; kt < 4; kt++) {
            const int kb = kt * 32 + qc * 4;
#pragma unroll
            for (int nt = 0; nt < 8; nt++) {
                const char* kp = sm + (nt * 8 + qr) * ATS + kb;
                uint32_t kbh[2], kbl[2];
                kbh[0] = *(const uint32_t*)kp;
                kbh[1] = *(const uint32_t*)(kp + 16);
                kbl[0] = *(const uint32_t*)(kp + KTILE);
                kbl[1] = *(const uint32_t*)(kp + KTILE + 16);
                mma16816(S[nt], qfh[kt], kbh);
                mma16816(S[nt], qfh[kt], kbl);
                mma16816(S[nt], qfl[kt], kbh);
            }
        }

        // ---- online softmax (base 2) ----
        float rx0 = -1e30f, rx1 = -1e30f;
#pragma unroll
        for (int nt = 0; nt < 8; nt++) {
            rx0 = fmaxf(rx0, fmaxf(S[nt][0], S[nt][1]));
            rx1 = fmaxf(rx1, fmaxf(S[nt][2], S[nt][3]));
        }
        rx0 = fmaxf(rx0, __shfl_xor_sync(0xffffffffu, rx0, 1));
        rx0 = fmaxf(rx0, __shfl_xor_sync(0xffffffffu, rx0, 2));
        rx1 = fmaxf(rx1, __shfl_xor_sync(0xffffffffu, rx1, 1));
        rx1 = fmaxf(rx1, __shfl_xor_sync(0xffffffffu, rx1, 2));

        const float mn0 = fmaxf(m0, rx0);
        const float mn1 = fmaxf(m1, rx1);
        const float a0 = ex2f(m0 - mn0);
        const float a1 = ex2f(m1 - mn1);
        m0 = mn0; m1 = mn1;
        l0 *= a0;  l1 *= a1;

#pragma unroll
        for (int nt = 0; nt < 8; nt++) {
            S[nt][0] = ex2f(S[nt][0] - m0);
            S[nt][1] = ex2f(S[nt][1] - m0);
            S[nt][2] = ex2f(S[nt][2] - m1);
            S[nt][3] = ex2f(S[nt][3] - m1);
            l0 += S[nt][0] + S[nt][1];
            l1 += S[nt][2] + S[nt][3];
            O[nt][0] *= a0; O[nt][1] *= a0;
            O[nt][2] *= a1; O[nt][3] *= a1;
        }

        // ---- O += P V (P split hi/lo in registers) ----
#pragma unroll
        for (int kt = 0; kt < 4; kt++) {
            uint32_t ph[4], pl[4];
#pragma unroll
            for (int half = 0; half < 2; half++) {      // half 0 -> keys +0..7 (ntile 2kt), 1 -> +8..15
                const float* sv = S[2 * kt + half];
                __nv_bfloat16 h0 = __float2bfloat16(sv[0]);
                __nv_bfloat16 h1 = __float2bfloat16(sv[1]);
                __nv_bfloat16 h2 = __float2bfloat16(sv[2]);
                __nv_bfloat16 h3 = __float2bfloat16(sv[3]);
                ph[half * 2 + 0] = (uint32_t)__bfloat16_as_ushort(h0) |
                                   ((uint32_t)__bfloat16_as_ushort(h1) << 16);
                ph[half * 2 + 1] = (uint32_t)__bfloat16_as_ushort(h2) |
                                   ((uint32_t)__bfloat16_as_ushort(h3) << 16);
                pl[half * 2 + 0] = pack_bf2(sv[0] - __bfloat162float(h0),
                                            sv[1] - __bfloat162float(h1));
                pl[half * 2 + 1] = pack_bf2(sv[2] - __bfloat162float(h2),
                                            sv[3] - __bfloat162float(h3));
            }
            // reorder: A-frag = {a0=(qr,k0),a1=(qr+8,k0),a2=(qr,k8),a3=(qr+8,k8)}
            uint32_t ah[4] = {ph[0], ph[1], ph[2], ph[3]};
            uint32_t al[4] = {pl[0], pl[1], pl[2], pl[3]};

            const int kb = kt * 32 + qc * 4;
#pragma unroll
            for (int nt = 0; nt < 8; nt++) {
                const char* vp = sm + 2 * KTILE + (nt * 8 + qr) * ATS + kb;
                uint32_t vbh[2], vbl[2];
                vbh[0] = *(const uint32_t*)vp;
                vbh[1] = *(const uint32_t*)(vp + 16);
                vbl[0] = *(const uint32_t*)(vp + KTILE);
                vbl[1] = *(const uint32_t*)(vp + KTILE + 16);
                mma16816(O[nt], ah, vbh);
                mma16816(O[nt], ah, vbl);
                mma16816(O[nt], al, vbh);
            }
        }
    }

    // ---- finalize: reduce l across quad lanes, normalize, store ----
    l0 += __shfl_xor_sync(0xffffffffu, l0, 1);
    l0 += __shfl_xor_sync(0xffffffffu, l0, 2);
    l1 += __shfl_xor_sync(0xffffffffu, l1, 1);
    l1 += __shfl_xor_sync(0xffffffffu, l1, 2);
    const float inv0 = 1.f / l0, inv1 = 1.f / l1;

    const int s = s0 + wid * 16 + qr;
#pragma unroll
    for (int nt = 0; nt < 8; nt++) {
        const int col = h * DK + nt * 8 + qc * 2;
        float2 r0; r0.x = O[nt][0] * inv0; r0.y = O[nt][1] * inv0;
        float2 r1; r1.x = O[nt][2] * inv1; r1.y = O[nt][3] * inv1;
        *(float2*)(Ctx + ((size_t)(b * SEQ + s)     ) * DMODEL + col) = r0;
        *(float2*)(Ctx + ((size_t)(b * SEQ + s + 8) ) * DMODEL + col) = r1;
    }
}

// ---------------- launch ---------------------------------------------------
extern "C" void kernel_launch(void* const* d_in, const int* in_sizes, int n_in,
                              void* d_out, int out_size)
{
    (void)in_sizes; (void)n_in; (void)out_size;
    const float* q    = (const float*)d_in[0];
    const float* k    = (const float*)d_in[1];
    const float* v    = (const float*)d_in[2];
    const float* wq_w = (const float*)d_in[4];
    const float* wq_b = (const float*)d_in[5];
    const float* wk_w = (const float*)d_in[6];
    const float* wk_b = (const float*)d_in[7];
    const float* wv_w = (const float*)d_in[8];
    const float* wv_b = (const float*)d_in[9];
    const float* wo_w = (const float*)d_in[10];
    const float* wo_b = (const float*)d_in[11];
    float* out = (float*)d_out;

    float* ctx;
    cudaGetSymbolAddress((void**)&ctx, g_ctx);

    __nv_bfloat16 *qhi, *qlo, *khi, *klo, *vhi, *vlo, *chi, *clo;
    __nv_bfloat16 *wqhi, *wqlo, *wkhi, *wklo, *wvhi, *wvlo, *wohi, *wolo;
    __nv_bfloat16 *qshi, *qslo, *kshi, *kslo, *vthi, *vtlo;
    cudaGetSymbolAddress((void**)&qhi, g_qhi);  cudaGetSymbolAddress((void**)&qlo, g_qlo);
    cudaGetSymbolAddress((void**)&khi, g_khi);  cudaGetSymbolAddress((void**)&klo, g_klo);
    cudaGetSymbolAddress((void**)&vhi, g_vhi);  cudaGetSymbolAddress((void**)&vlo, g_vlo);
    cudaGetSymbolAddress((void**)&chi, g_chi);  cudaGetSymbolAddress((void**)&clo, g_clo);
    cudaGetSymbolAddress((void**)&wqhi, g_wqhi); cudaGetSymbolAddress((void**)&wqlo, g_wqlo);
    cudaGetSymbolAddress((void**)&wkhi, g_wkhi); cudaGetSymbolAddress((void**)&wklo, g_wklo);
    cudaGetSymbolAddress((void**)&wvhi, g_wvhi); cudaGetSymbolAddress((void**)&wvlo, g_wvlo);
    cudaGetSymbolAddress((void**)&wohi, g_wohi); cudaGetSymbolAddress((void**)&wolo, g_wolo);
    cudaGetSymbolAddress((void**)&qshi, g_qshi); cudaGetSymbolAddress((void**)&qslo, g_qslo);
    cudaGetSymbolAddress((void**)&kshi, g_kshi); cudaGetSymbolAddress((void**)&kslo, g_kslo);
    cudaGetSymbolAddress((void**)&vthi, g_vthi); cudaGetSymbolAddress((void**)&vtlo, g_vtlo);

    const int nAct4 = MROWS * DMODEL / 4;
    const int nW4   = DMODEL * DMODEL / 4;

    split_bf16_k<<<(nAct4 + 255) / 256, 256>>>((const float4*)q, (uint2*)qhi, (uint2*)qlo, nAct4);
    split_bf16_k<<<(nAct4 + 255) / 256, 256>>>((const float4*)k, (uint2*)khi, (uint2*)klo, nAct4);
    split_bf16_k<<<(nAct4 + 255) / 256, 256>>>((const float4*)v, (uint2*)vhi, (uint2*)vlo, nAct4);
    split_bf16_k<<<(nW4 + 255) / 256, 256>>>((const float4*)wq_w, (uint2*)wqhi, (uint2*)wqlo, nW4);
    split_bf16_k<<<(nW4 + 255) / 256, 256>>>((const float4*)wk_w, (uint2*)wkhi, (uint2*)wklo, nW4);
    split_bf16_k<<<(nW4 + 255) / 256, 256>>>((const float4*)wv_w, (uint2*)wvhi, (uint2*)wvlo, nW4);
    split_bf16_k<<<(nW4 + 255) / 256, 256>>>((const float4*)wo_w, (uint2*)wohi, (uint2*)wolo, nW4);

    // (1/sqrt(64)) * log2(e): score scale folded into Q projection (base-2 softmax)
    const float qscale = 0.125f * 1.4426950408889634f;

    dim3 ggrid(DMODEL / 128, MROWS / 128);   // (8, 32)
    gemm_mma<1><<<ggrid, 256, GEMM_SMEM>>>(qhi, qlo, wqhi, wqlo, wq_b, qscale,
                                           nullptr, qshi, qslo);
    gemm_mma<1><<<ggrid, 256, GEMM_SMEM>>>(khi, klo, wkhi, wklo, wk_b, 1.0f,
                                           nullptr, kshi, kslo);
    gemm_mma<2><<<ggrid, 256, GEMM_SMEM>>>(vhi, vlo, wvhi, wvlo, wv_b, 1.0f,
                                           nullptr, vthi, vtlo);

    dim3 agrid(SEQ / 128, BH);               // (16, 32)
    flash_mma<<<agrid, 256>>>(qshi, qslo, kshi, kslo, vthi, vtlo, ctx);

    split_bf16_k<<<(nAct4 + 255) / 256, 256>>>((const float4*)ctx, (uint2*)chi, (uint2*)clo, nAct4);
    gemm_mma<0><<<ggrid, 256, GEMM_SMEM>>>(chi, clo, wohi, wolo, wo_b, 1.0f,
                                           out, nullptr, nullptr);
}